// round 6
// baseline (speedup 1.0000x reference)
#include <cuda_runtime.h>
#include <cstdint>

#define ALPHAF 0.3f
#define EPSF   1e-8f
#define PATW   0.1f

// ---- dynamic smem layout (bytes) ----
#define O_X    0        // X staging: 128 rows x 72 halfs (144B stride) = 18432
#define O_B1   18432    // B1 image: 64 rows x 72 halfs  (wh|wl) = 9216
#define O_B2   27648    // B2 image: 32 rows x 136 halfs (wh|wl) = 8704
#define O_G    36352    // grid tile fp32: 128 x 33 = 16896
#define O_P    53248    // pot: 128 f32
#define O_B1S  53760    // b1: 64 f32
#define O_W1P  54016    // W1[32][:]: 64 f32
#define O_B2S  54272    // b2: 32 f32
#define SMEMSZ 54400

#define XSTR  72   // halfs
#define B1STR 72
#define B2STR 136

// Pre-split weight images (B1: 64x72 halfs, then B2: 32x136 halfs), built once.
__device__ __align__(16) unsigned char gWimg[17920];

static __device__ __forceinline__ void ldm4(uint32_t* r, uint32_t addr) {
    asm volatile("ldmatrix.sync.aligned.m8n8.x4.shared.b16 {%0,%1,%2,%3}, [%4];"
                 : "=r"(r[0]), "=r"(r[1]), "=r"(r[2]), "=r"(r[3]) : "r"(addr));
}
static __device__ __forceinline__ void mma16816(float* c, const uint32_t* a, const uint32_t* b) {
    asm volatile(
        "mma.sync.aligned.m16n8k16.row.col.f32.bf16.bf16.f32 "
        "{%0,%1,%2,%3},{%4,%5,%6,%7},{%8,%9},{%0,%1,%2,%3};"
        : "+f"(c[0]), "+f"(c[1]), "+f"(c[2]), "+f"(c[3])
        : "r"(a[0]), "r"(a[1]), "r"(a[2]), "r"(a[3]), "r"(b[0]), "r"(b[1]));
}
static __device__ __forceinline__ unsigned short bfbits(float v) {
    unsigned short r;
    asm("cvt.rn.bf16.f32 %0, %1;" : "=h"(r) : "f"(v));
    return r;
}
static __device__ __forceinline__ float bf2f(unsigned short b) {
    return __uint_as_float((uint32_t)b << 16);
}
static __device__ __forceinline__ uint32_t packbf2(float lo, float hi) {
    uint32_t r;
    asm("cvt.rn.bf16x2.f32 %0, %1, %2;" : "=r"(r) : "f"(hi), "f"(lo));
    return r;
}

// ---- prep: build split weight images once (identical for all CTAs) ----
__global__ void be_prep(const float* __restrict__ W1, const float* __restrict__ W2) {
    int i = blockIdx.x * 256 + threadIdx.x;
    unsigned short* img = (unsigned short*)gWimg;
    if (i < 4608) {                       // B1: [n<64][k<72]
        int n = i / 72, k = i % 72;
        unsigned short bits = 0;
        if (k < 32) bits = bfbits(W1[k * 64 + n]);
        else if (k < 64) {
            float v = W1[(k - 32) * 64 + n];
            bits = bfbits(v - bf2f(bfbits(v)));
        }
        img[i] = bits;
    } else if (i < 8960) {                // B2: [n<32][k<136]
        int j = i - 4608;
        int n = j / 136, k = j % 136;
        unsigned short bits = 0;
        if (k < 64) bits = bfbits(W2[k * 32 + n]);
        else if (k < 128) {
            float v = W2[(k - 64) * 32 + n];
            bits = bfbits(v - bf2f(bfbits(v)));
        }
        img[i] = bits;
    }
}

__global__ void __launch_bounds__(128, 4)
be_mma(const float* __restrict__ grid, const float* __restrict__ pot,
       const float* __restrict__ W1,   const float* __restrict__ b1,
       const float* __restrict__ W2,   const float* __restrict__ b2,
       float* __restrict__ out)
{
    extern __shared__ __align__(16) unsigned char sm[];
    float* gsm = (float*)(sm + O_G);
    float* psm = (float*)(sm + O_P);
    float* b1s = (float*)(sm + O_B1S);
    float* w1p = (float*)(sm + O_W1P);
    float* b2s = (float*)(sm + O_B2S);

    const int tid  = threadIdx.x;
    const int lane = tid & 31;
    const int w    = tid >> 5;

    const uint32_t xs_b = (uint32_t)__cvta_generic_to_shared(sm + O_X);
    const uint32_t b1_b = (uint32_t)__cvta_generic_to_shared(sm + O_B1);
    const uint32_t b2_b = (uint32_t)__cvta_generic_to_shared(sm + O_B2);

    // ---- stage grid tile (coalesced LDG.128 -> conflict-free STS) ----
    {
        const uint4* gsrc = (const uint4*)(grid + (size_t)blockIdx.x * 4096);
        #pragma unroll
        for (int j = 0; j < 8; j++) {
            int e4 = tid + 128 * j;
            uint4 v = gsrc[e4];
            int row = e4 >> 3, c = (e4 & 7) * 4;
            float* d = gsm + row * 33 + c;
            d[0] = __uint_as_float(v.x); d[1] = __uint_as_float(v.y);
            d[2] = __uint_as_float(v.z); d[3] = __uint_as_float(v.w);
        }
    }
    psm[tid] = pot[(size_t)blockIdx.x * 128 + tid];

    // ---- weight images: coalesced copy of the pre-built global image ----
    {
        const uint4* src = (const uint4*)gWimg;
        uint4*       dst = (uint4*)(sm + O_B1);      // B1 then B2, contiguous
        #pragma unroll
        for (int i = tid; i < 1120; i += 128) dst[i] = src[i];
    }
    if (tid < 64) { b1s[tid] = b1[tid]; w1p[tid] = W1[32 * 64 + tid]; }
    if (tid < 32) b2s[tid] = b2[tid];
    __syncthreads();

    // ---- per-pixel x = g + 0.1 * g^3/(||g^3||+eps)*||g||, split hi/lo ----
    {
        float gv[32];
        #pragma unroll
        for (int c = 0; c < 32; c++) gv[c] = gsm[tid * 33 + c];
        float gn2 = 0.f, cn2 = 0.f;
        #pragma unroll
        for (int i = 0; i < 32; i++) {
            float q = gv[i] * gv[i];
            gn2 += q;
            float c3 = q * gv[i];
            cn2 = fmaf(c3, c3, cn2);
        }
        const float t = PATW * sqrtf(gn2) / (sqrtf(cn2) + EPSF);
        uint32_t xh[16], xl[16];
        #pragma unroll
        for (int i = 0; i < 16; i++) {
            float x0 = fmaf(t * gv[2*i]   * gv[2*i],   gv[2*i],   gv[2*i]);
            float x1 = fmaf(t * gv[2*i+1] * gv[2*i+1], gv[2*i+1], gv[2*i+1]);
            uint32_t p = packbf2(x0, x1);
            xh[i] = p;
            float l0 = x0 - __uint_as_float(p << 16);
            float l1 = x1 - __uint_as_float(p & 0xFFFF0000u);
            xl[i] = packbf2(l0, l1);
        }
        uint4* xr = (uint4*)(sm + O_X + tid * (XSTR * 2));
        #pragma unroll
        for (int j = 0; j < 4; j++)
            xr[j] = make_uint4(xh[4*j], xh[4*j+1], xh[4*j+2], xh[4*j+3]);
        #pragma unroll
        for (int j = 0; j < 4; j++)
            xr[4 + j] = make_uint4(xl[4*j], xl[4*j+1], xl[4*j+2], xl[4*j+3]);
    }
    __syncwarp();

    const int m0 = w * 32;

    // ---- A fragments (xh cols 0..31, xl cols 32..63) ----
    uint32_t Ah[2][2][4], Al[2][2][4];
    #pragma unroll
    for (int mt = 0; mt < 2; mt++)
        #pragma unroll
        for (int ks = 0; ks < 2; ks++) {
            uint32_t base = xs_b + (uint32_t)(m0 + mt*16 + (lane & 15)) * (XSTR*2)
                          + ((lane >> 4) << 4);
            ldm4(Ah[mt][ks], base + (uint32_t)(ks*16) * 2);
            ldm4(Al[mt][ks], base + (uint32_t)(32 + ks*16) * 2);
        }

    // ---- B1 wh fragments ----
    uint32_t Bf[2][8][2];
    #pragma unroll
    for (int ks = 0; ks < 2; ks++)
        #pragma unroll
        for (int np = 0; np < 4; np++) {
            uint32_t a = b1_b + (uint32_t)(np*16 + ((lane>>4)<<3) + (lane&7)) * (B1STR*2)
                       + (uint32_t)(ks*16)*2 + (((lane>>3)&1) << 4);
            ldm4(&Bf[ks][2*np][0], a);
        }

    // ---- C1 init: b1[n] + pot[m]*W1[32][n] (fp32 exact) ----
    float C[2][8][4];
    const int nb = (lane & 3) * 2;
    float pv[2][2];
    #pragma unroll
    for (int mt = 0; mt < 2; mt++) {
        pv[mt][0] = psm[m0 + mt*16 + (lane >> 2)];
        pv[mt][1] = psm[m0 + mt*16 + (lane >> 2) + 8];
    }
    #pragma unroll
    for (int nt = 0; nt < 8; nt++) {
        int n = nt*8 + nb;
        float bb0 = b1s[n], bb1 = b1s[n+1], w0 = w1p[n], w1v = w1p[n+1];
        #pragma unroll
        for (int mt = 0; mt < 2; mt++) {
            C[mt][nt][0] = fmaf(pv[mt][0], w0,  bb0);
            C[mt][nt][1] = fmaf(pv[mt][0], w1v, bb1);
            C[mt][nt][2] = fmaf(pv[mt][1], w0,  bb0);
            C[mt][nt][3] = fmaf(pv[mt][1], w1v, bb1);
        }
    }

    // ---- GEMM1: xh*wh + xl*wh, then xh*wl ----
    #pragma unroll
    for (int ks = 0; ks < 2; ks++)
        #pragma unroll
        for (int mt = 0; mt < 2; mt++)
            #pragma unroll
            for (int nt = 0; nt < 8; nt++)
                mma16816(C[mt][nt], Ah[mt][ks], Bf[ks][nt]);
    #pragma unroll
    for (int ks = 0; ks < 2; ks++)
        #pragma unroll
        for (int mt = 0; mt < 2; mt++)
            #pragma unroll
            for (int nt = 0; nt < 8; nt++)
                mma16816(C[mt][nt], Al[mt][ks], Bf[ks][nt]);
    #pragma unroll
    for (int ks = 0; ks < 2; ks++)                 // reload B with wl (cols 32..63)
        #pragma unroll
        for (int np = 0; np < 4; np++) {
            uint32_t a = b1_b + (uint32_t)(np*16 + ((lane>>4)<<3) + (lane&7)) * (B1STR*2)
                       + (uint32_t)(32 + ks*16)*2 + (((lane>>3)&1) << 4);
            ldm4(&Bf[ks][2*np][0], a);
        }
    #pragma unroll
    for (int ks = 0; ks < 2; ks++)
        #pragma unroll
        for (int mt = 0; mt < 2; mt++)
            #pragma unroll
            for (int nt = 0; nt < 8; nt++)
                mma16816(C[mt][nt], Ah[mt][ks], Bf[ks][nt]);

    // ---- relu + split -> A2 fragments straight from C regs ----
    uint32_t Hh[2][4][4], Hl[2][4][4];
    #pragma unroll
    for (int mt = 0; mt < 2; mt++)
        #pragma unroll
        for (int ks = 0; ks < 4; ks++)
            #pragma unroll
            for (int q = 0; q < 4; q++) {
                int nt = 2*ks + (q >> 1);
                float hA = fmaxf(C[mt][nt][(q & 1) * 2],     0.f);
                float hB = fmaxf(C[mt][nt][(q & 1) * 2 + 1], 0.f);
                uint32_t p = packbf2(hA, hB);
                Hh[mt][ks][q] = p;
                float lA = hA - __uint_as_float(p << 16);
                float lB = hB - __uint_as_float(p & 0xFFFF0000u);
                Hl[mt][ks][q] = packbf2(lA, lB);
            }

    // ---- GEMM2: hh*w2h + hl*w2h, then hh*w2l ----
    float C2[2][4][4];
    #pragma unroll
    for (int mt = 0; mt < 2; mt++)
        #pragma unroll
        for (int nt = 0; nt < 4; nt++)
            #pragma unroll
            for (int q = 0; q < 4; q++) C2[mt][nt][q] = 0.f;

    uint32_t B2f[4][2];
    #pragma unroll
    for (int ks = 0; ks < 4; ks++) {
        #pragma unroll
        for (int np = 0; np < 2; np++) {
            uint32_t a = b2_b + (uint32_t)(np*16 + ((lane>>4)<<3) + (lane&7)) * (B2STR*2)
                       + (uint32_t)(ks*16)*2 + (((lane>>3)&1) << 4);
            ldm4(&B2f[2*np][0], a);
        }
        #pragma unroll
        for (int mt = 0; mt < 2; mt++)
            #pragma unroll
            for (int nt = 0; nt < 4; nt++) {
                mma16816(C2[mt][nt], Hh[mt][ks], B2f[nt]);
                mma16816(C2[mt][nt], Hl[mt][ks], B2f[nt]);
            }
    }
    #pragma unroll
    for (int ks = 0; ks < 4; ks++) {
        #pragma unroll
        for (int np = 0; np < 2; np++) {
            uint32_t a = b2_b + (uint32_t)(np*16 + ((lane>>4)<<3) + (lane&7)) * (B2STR*2)
                       + (uint32_t)(64 + ks*16)*2 + (((lane>>3)&1) << 4);
            ldm4(&B2f[2*np][0], a);
        }
        #pragma unroll
        for (int mt = 0; mt < 2; mt++)
            #pragma unroll
            for (int nt = 0; nt < 4; nt++)
                mma16816(C2[mt][nt], Hh[mt][ks], B2f[nt]);
    }

    // ---- epilogue: RMW alpha*g into gsm (own rows per warp), then coalesced STG ----
    #pragma unroll
    for (int mt = 0; mt < 2; mt++) {
        int r0 = m0 + mt*16 + (lane >> 2);
        int r1 = r0 + 8;
        #pragma unroll
        for (int nt = 0; nt < 4; nt++) {
            int n = nt*8 + nb;
            float bb0 = b2s[n], bb1 = b2s[n+1];
            gsm[r0*33 + n]     = fmaf(ALPHAF, gsm[r0*33 + n],     C2[mt][nt][0] + bb0);
            gsm[r0*33 + n + 1] = fmaf(ALPHAF, gsm[r0*33 + n + 1], C2[mt][nt][1] + bb1);
            gsm[r1*33 + n]     = fmaf(ALPHAF, gsm[r1*33 + n],     C2[mt][nt][2] + bb0);
            gsm[r1*33 + n + 1] = fmaf(ALPHAF, gsm[r1*33 + n + 1], C2[mt][nt][3] + bb1);
        }
    }
    __syncthreads();

    {
        float4* outb = (float4*)(out + (size_t)blockIdx.x * 4096);
        #pragma unroll
        for (int j = 0; j < 8; j++) {
            int e4 = tid + 128 * j;
            int row = e4 >> 3, c = (e4 & 7) * 4;
            const float* s = gsm + row * 33 + c;
            outb[e4] = make_float4(s[0], s[1], s[2], s[3]);
        }
    }
}

extern "C" void kernel_launch(void* const* d_in, const int* in_sizes, int n_in,
                              void* d_out, int out_size) {
    const float* grid = (const float*)d_in[0];
    const float* pot  = (const float*)d_in[1];
    const float* W1   = (const float*)d_in[2];
    const float* b1   = (const float*)d_in[3];
    const float* W2   = (const float*)d_in[4];
    const float* b2   = (const float*)d_in[5];
    float* out = (float*)d_out;

    cudaFuncSetAttribute(be_mma, cudaFuncAttributeMaxDynamicSharedMemorySize, SMEMSZ);

    be_prep<<<35, 256>>>(W1, W2);
    be_mma<<<8192, 128, SMEMSZ>>>(grid, pot, W1, b1, W2, b2, out);
}

// round 7
// speedup vs baseline: 1.0132x; 1.0132x over previous
#include <cuda_runtime.h>
#include <cstdint>

#define ALPHAF 0.3f
#define EPSF   1e-8f
#define PATW   0.1f

// ---- dynamic smem layout (bytes) ----
#define O_X    0        // X staging: 128 rows x 72 halfs (144B stride) = 18432
                        //   (also used first as raw-weight staging: 16640B)
#define O_B1   18432    // B1 image: 64 rows x 72 halfs  (wh|wl) = 9216
#define O_B2   27648    // B2 image: 32 rows x 136 halfs (wh|wl) = 8704
#define O_G    36352    // grid tile fp32: 128 x 33 = 16896
#define O_P    53248    // pot: 128 f32
#define O_B1S  53760    // b1: 64 f32
#define O_W1P  54016    // W1[32][:]: 64 f32
#define O_B2S  54272    // b2: 32 f32
#define SMEMSZ 54400

#define XSTR  72   // halfs
#define B1STR 72
#define B2STR 136

static __device__ __forceinline__ void ldm4(uint32_t* r, uint32_t addr) {
    asm volatile("ldmatrix.sync.aligned.m8n8.x4.shared.b16 {%0,%1,%2,%3}, [%4];"
                 : "=r"(r[0]), "=r"(r[1]), "=r"(r[2]), "=r"(r[3]) : "r"(addr));
}
static __device__ __forceinline__ void mma16816(float* c, const uint32_t* a, const uint32_t* b) {
    asm volatile(
        "mma.sync.aligned.m16n8k16.row.col.f32.bf16.bf16.f32 "
        "{%0,%1,%2,%3},{%4,%5,%6,%7},{%8,%9},{%0,%1,%2,%3};"
        : "+f"(c[0]), "+f"(c[1]), "+f"(c[2]), "+f"(c[3])
        : "r"(a[0]), "r"(a[1]), "r"(a[2]), "r"(a[3]), "r"(b[0]), "r"(b[1]));
}
static __device__ __forceinline__ unsigned short bfbits(float v) {
    unsigned short r;
    asm("cvt.rn.bf16.f32 %0, %1;" : "=h"(r) : "f"(v));
    return r;
}
static __device__ __forceinline__ float bf2f(unsigned short b) {
    return __uint_as_float((uint32_t)b << 16);
}
static __device__ __forceinline__ uint32_t packbf2(float lo, float hi) {
    uint32_t r;
    asm("cvt.rn.bf16x2.f32 %0, %1, %2;" : "=r"(r) : "f"(hi), "f"(lo));
    return r;
}
static __device__ __forceinline__ uint32_t split2(float v0, float v1, uint32_t& plo) {
    unsigned short h0 = bfbits(v0), h1 = bfbits(v1);
    unsigned short l0 = bfbits(v0 - bf2f(h0));
    unsigned short l1 = bfbits(v1 - bf2f(h1));
    plo = (uint32_t)l0 | ((uint32_t)l1 << 16);
    return (uint32_t)h0 | ((uint32_t)h1 << 16);
}

__global__ void __launch_bounds__(128, 4)
be_mma(const float* __restrict__ grid, const float* __restrict__ pot,
       const float* __restrict__ W1,   const float* __restrict__ b1,
       const float* __restrict__ W2,   const float* __restrict__ b2,
       float* __restrict__ out)
{
    extern __shared__ __align__(16) unsigned char sm[];
    float* gsm = (float*)(sm + O_G);
    float* psm = (float*)(sm + O_P);
    float* b1s = (float*)(sm + O_B1S);
    float* w1p = (float*)(sm + O_W1P);
    float* b2s = (float*)(sm + O_B2S);
    float* rw1 = (float*)(sm + O_X);            // raw W1: 2112 f32 (8448 B)
    float* rw2 = (float*)(sm + O_X + 8448);     // raw W2: 2048 f32 (8192 B)
    unsigned short* img1 = (unsigned short*)(sm + O_B1);
    unsigned short* img2 = (unsigned short*)(sm + O_B2);

    const int tid  = threadIdx.x;
    const int lane = tid & 31;
    const int w    = tid >> 5;

    const uint32_t xs_b = (uint32_t)__cvta_generic_to_shared(sm + O_X);
    const uint32_t b1_b = (uint32_t)__cvta_generic_to_shared(sm + O_B1);
    const uint32_t b2_b = (uint32_t)__cvta_generic_to_shared(sm + O_B2);

    // ---- phase 1: all global loads issue up-front (independent LDGs) ----
    {
        const uint4* gsrc = (const uint4*)(grid + (size_t)blockIdx.x * 4096);
        #pragma unroll
        for (int j = 0; j < 8; j++) {
            int e4 = tid + 128 * j;
            uint4 v = gsrc[e4];
            int row = e4 >> 3, c = (e4 & 7) * 4;
            float* d = gsm + row * 33 + c;
            d[0] = __uint_as_float(v.x); d[1] = __uint_as_float(v.y);
            d[2] = __uint_as_float(v.z); d[3] = __uint_as_float(v.w);
        }
    }
    psm[tid] = pot[(size_t)blockIdx.x * 128 + tid];
    #pragma unroll
    for (int i = tid; i < 2112; i += 128) rw1[i] = W1[i];
    #pragma unroll
    for (int i = tid; i < 2048; i += 128) rw2[i] = W2[i];
    if (tid < 64) b1s[tid] = b1[tid];
    if (tid < 32) b2s[tid] = b2[tid];
    __syncthreads();

    // ---- phase 2: smem-side transpose + bf16 hi/lo split (coalesced) ----
    if (tid < 64) {                         // W1 column n = tid
        const int n = tid;
        uint32_t ph[16], pl[16];
        #pragma unroll
        for (int kk = 0; kk < 16; kk++)
            ph[kk] = split2(rw1[(2*kk)*64 + n], rw1[(2*kk+1)*64 + n], pl[kk]);
        uint4* dh = (uint4*)(img1 + n * B1STR);
        uint4* dl = (uint4*)(img1 + n * B1STR + 32);
        #pragma unroll
        for (int q = 0; q < 4; q++) {
            dh[q] = make_uint4(ph[4*q], ph[4*q+1], ph[4*q+2], ph[4*q+3]);
            dl[q] = make_uint4(pl[4*q], pl[4*q+1], pl[4*q+2], pl[4*q+3]);
        }
        w1p[n] = rw1[32 * 64 + n];
    } else {                                // W2 column n2, half kh
        const int n2 = (tid - 64) >> 1;
        const int kh = (tid & 1) * 32;
        uint32_t ph[16], pl[16];
        #pragma unroll
        for (int kk = 0; kk < 16; kk++) {
            int k = kh + 2 * kk;
            ph[kk] = split2(rw2[k*32 + n2], rw2[(k+1)*32 + n2], pl[kk]);
        }
        uint4* dh = (uint4*)(img2 + n2 * B2STR + kh);
        uint4* dl = (uint4*)(img2 + n2 * B2STR + 64 + kh);
        #pragma unroll
        for (int q = 0; q < 4; q++) {
            dh[q] = make_uint4(ph[4*q], ph[4*q+1], ph[4*q+2], ph[4*q+3]);
            dl[q] = make_uint4(pl[4*q], pl[4*q+1], pl[4*q+2], pl[4*q+3]);
        }
    }
    __syncthreads();    // conversion reads of rw done before X overwrites

    // ---- phase 3: per-pixel x = g + 0.1*g^3/(||g^3||+eps)*||g||, split ----
    {
        float gv[32];
        #pragma unroll
        for (int c = 0; c < 32; c++) gv[c] = gsm[tid * 33 + c];
        float gn2 = 0.f, cn2 = 0.f;
        #pragma unroll
        for (int i = 0; i < 32; i++) {
            float q = gv[i] * gv[i];
            gn2 += q;
            float c3 = q * gv[i];
            cn2 = fmaf(c3, c3, cn2);
        }
        const float t = PATW * sqrtf(gn2) / (sqrtf(cn2) + EPSF);
        uint32_t xh[16], xl[16];
        #pragma unroll
        for (int i = 0; i < 16; i++) {
            float x0 = fmaf(t * gv[2*i]   * gv[2*i],   gv[2*i],   gv[2*i]);
            float x1 = fmaf(t * gv[2*i+1] * gv[2*i+1], gv[2*i+1], gv[2*i+1]);
            uint32_t p = packbf2(x0, x1);
            xh[i] = p;
            float l0 = x0 - __uint_as_float(p << 16);
            float l1 = x1 - __uint_as_float(p & 0xFFFF0000u);
            xl[i] = packbf2(l0, l1);
        }
        uint4* xr = (uint4*)(sm + O_X + tid * (XSTR * 2));
        #pragma unroll
        for (int j = 0; j < 4; j++)
            xr[j] = make_uint4(xh[4*j], xh[4*j+1], xh[4*j+2], xh[4*j+3]);
        #pragma unroll
        for (int j = 0; j < 4; j++)
            xr[4 + j] = make_uint4(xl[4*j], xl[4*j+1], xl[4*j+2], xl[4*j+3]);
    }
    __syncwarp();

    const int m0 = w * 32;

    // ---- A fragments (xh cols 0..31, xl cols 32..63) ----
    uint32_t Ah[2][2][4], Al[2][2][4];
    #pragma unroll
    for (int mt = 0; mt < 2; mt++)
        #pragma unroll
        for (int ks = 0; ks < 2; ks++) {
            uint32_t base = xs_b + (uint32_t)(m0 + mt*16 + (lane & 15)) * (XSTR*2)
                          + ((lane >> 4) << 4);
            ldm4(Ah[mt][ks], base + (uint32_t)(ks*16) * 2);
            ldm4(Al[mt][ks], base + (uint32_t)(32 + ks*16) * 2);
        }

    // ---- B1 wh fragments ----
    uint32_t Bf[2][8][2];
    #pragma unroll
    for (int ks = 0; ks < 2; ks++)
        #pragma unroll
        for (int np = 0; np < 4; np++) {
            uint32_t a = b1_b + (uint32_t)(np*16 + ((lane>>4)<<3) + (lane&7)) * (B1STR*2)
                       + (uint32_t)(ks*16)*2 + (((lane>>3)&1) << 4);
            ldm4(&Bf[ks][2*np][0], a);
        }

    // ---- C1 init: b1[n] + pot[m]*W1[32][n] (fp32 exact) ----
    float C[2][8][4];
    const int nb = (lane & 3) * 2;
    float pv[2][2];
    #pragma unroll
    for (int mt = 0; mt < 2; mt++) {
        pv[mt][0] = psm[m0 + mt*16 + (lane >> 2)];
        pv[mt][1] = psm[m0 + mt*16 + (lane >> 2) + 8];
    }
    #pragma unroll
    for (int nt = 0; nt < 8; nt++) {
        int n = nt*8 + nb;
        float bb0 = b1s[n], bb1 = b1s[n+1], w0 = w1p[n], w1v = w1p[n+1];
        #pragma unroll
        for (int mt = 0; mt < 2; mt++) {
            C[mt][nt][0] = fmaf(pv[mt][0], w0,  bb0);
            C[mt][nt][1] = fmaf(pv[mt][0], w1v, bb1);
            C[mt][nt][2] = fmaf(pv[mt][1], w0,  bb0);
            C[mt][nt][3] = fmaf(pv[mt][1], w1v, bb1);
        }
    }

    // ---- GEMM1: xh*wh + xl*wh, then xh*wl ----
    #pragma unroll
    for (int ks = 0; ks < 2; ks++)
        #pragma unroll
        for (int mt = 0; mt < 2; mt++)
            #pragma unroll
            for (int nt = 0; nt < 8; nt++)
                mma16816(C[mt][nt], Ah[mt][ks], Bf[ks][nt]);
    #pragma unroll
    for (int ks = 0; ks < 2; ks++)
        #pragma unroll
        for (int mt = 0; mt < 2; mt++)
            #pragma unroll
            for (int nt = 0; nt < 8; nt++)
                mma16816(C[mt][nt], Al[mt][ks], Bf[ks][nt]);
    #pragma unroll
    for (int ks = 0; ks < 2; ks++)                 // reload B with wl (cols 32..63)
        #pragma unroll
        for (int np = 0; np < 4; np++) {
            uint32_t a = b1_b + (uint32_t)(np*16 + ((lane>>4)<<3) + (lane&7)) * (B1STR*2)
                       + (uint32_t)(32 + ks*16)*2 + (((lane>>3)&1) << 4);
            ldm4(&Bf[ks][2*np][0], a);
        }
    #pragma unroll
    for (int ks = 0; ks < 2; ks++)
        #pragma unroll
        for (int mt = 0; mt < 2; mt++)
            #pragma unroll
            for (int nt = 0; nt < 8; nt++)
                mma16816(C[mt][nt], Ah[mt][ks], Bf[ks][nt]);

    // ---- relu + split -> A2 fragments straight from C regs ----
    uint32_t Hh[2][4][4], Hl[2][4][4];
    #pragma unroll
    for (int mt = 0; mt < 2; mt++)
        #pragma unroll
        for (int ks = 0; ks < 4; ks++)
            #pragma unroll
            for (int q = 0; q < 4; q++) {
                int nt = 2*ks + (q >> 1);
                float hA = fmaxf(C[mt][nt][(q & 1) * 2],     0.f);
                float hB = fmaxf(C[mt][nt][(q & 1) * 2 + 1], 0.f);
                uint32_t p = packbf2(hA, hB);
                Hh[mt][ks][q] = p;
                float lA = hA - __uint_as_float(p << 16);
                float lB = hB - __uint_as_float(p & 0xFFFF0000u);
                Hl[mt][ks][q] = packbf2(lA, lB);
            }

    // ---- GEMM2: hh*w2h + hl*w2h, then hh*w2l ----
    float C2[2][4][4];
    #pragma unroll
    for (int mt = 0; mt < 2; mt++)
        #pragma unroll
        for (int nt = 0; nt < 4; nt++)
            #pragma unroll
            for (int q = 0; q < 4; q++) C2[mt][nt][q] = 0.f;

    uint32_t B2f[4][2];
    #pragma unroll
    for (int ks = 0; ks < 4; ks++) {
        #pragma unroll
        for (int np = 0; np < 2; np++) {
            uint32_t a = b2_b + (uint32_t)(np*16 + ((lane>>4)<<3) + (lane&7)) * (B2STR*2)
                       + (uint32_t)(ks*16)*2 + (((lane>>3)&1) << 4);
            ldm4(&B2f[2*np][0], a);
        }
        #pragma unroll
        for (int mt = 0; mt < 2; mt++)
            #pragma unroll
            for (int nt = 0; nt < 4; nt++) {
                mma16816(C2[mt][nt], Hh[mt][ks], B2f[nt]);
                mma16816(C2[mt][nt], Hl[mt][ks], B2f[nt]);
            }
    }
    #pragma unroll
    for (int ks = 0; ks < 4; ks++) {
        #pragma unroll
        for (int np = 0; np < 2; np++) {
            uint32_t a = b2_b + (uint32_t)(np*16 + ((lane>>4)<<3) + (lane&7)) * (B2STR*2)
                       + (uint32_t)(64 + ks*16)*2 + (((lane>>3)&1) << 4);
            ldm4(&B2f[2*np][0], a);
        }
        #pragma unroll
        for (int mt = 0; mt < 2; mt++)
            #pragma unroll
            for (int nt = 0; nt < 4; nt++)
                mma16816(C2[mt][nt], Hh[mt][ks], B2f[nt]);
    }

    // ---- epilogue: RMW alpha*g into gsm, then coalesced STG ----
    #pragma unroll
    for (int mt = 0; mt < 2; mt++) {
        int r0 = m0 + mt*16 + (lane >> 2);
        int r1 = r0 + 8;
        #pragma unroll
        for (int nt = 0; nt < 4; nt++) {
            int n = nt*8 + nb;
            float bb0 = b2s[n], bb1 = b2s[n+1];
            gsm[r0*33 + n]     = fmaf(ALPHAF, gsm[r0*33 + n],     C2[mt][nt][0] + bb0);
            gsm[r0*33 + n + 1] = fmaf(ALPHAF, gsm[r0*33 + n + 1], C2[mt][nt][1] + bb1);
            gsm[r1*33 + n]     = fmaf(ALPHAF, gsm[r1*33 + n],     C2[mt][nt][2] + bb0);
            gsm[r1*33 + n + 1] = fmaf(ALPHAF, gsm[r1*33 + n + 1], C2[mt][nt][3] + bb1);
        }
    }
    __syncthreads();

    {
        float4* outb = (float4*)(out + (size_t)blockIdx.x * 4096);
        #pragma unroll
        for (int j = 0; j < 8; j++) {
            int e4 = tid + 128 * j;
            int row = e4 >> 3, c = (e4 & 7) * 4;
            const float* s = gsm + row * 33 + c;
            outb[e4] = make_float4(s[0], s[1], s[2], s[3]);
        }
    }
}

extern "C" void kernel_launch(void* const* d_in, const int* in_sizes, int n_in,
                              void* d_out, int out_size) {
    const float* grid = (const float*)d_in[0];
    const float* pot  = (const float*)d_in[1];
    const float* W1   = (const float*)d_in[2];
    const float* b1   = (const float*)d_in[3];
    const float* W2   = (const float*)d_in[4];
    const float* b2   = (const float*)d_in[5];
    float* out = (float*)d_out;

    cudaFuncSetAttribute(be_mma, cudaFuncAttributeMaxDynamicSharedMemorySize, SMEMSZ);
    be_mma<<<8192, 128, SMEMSZ>>>(grid, pot, W1, b1, W2, b2, out);
}